// round 16
// baseline (speedup 1.0000x reference)
#include <cuda_runtime.h>

namespace {
constexpr int THREADS = 512;
constexpr int CH_STRIDE = 64 * 4 * 16 * 2 * 8;     // 65536 floats / batch
constexpr int NU = 2 * 4 * 2 * 8 * 16;             // 2048
constexpr int PRED_STRIDE = NU + 2 * 2 * 8 * 16;   // 2560
constexpr int A_LD = 66;
constexpr int NRHS = 16;
constexpr int CH_J = 32;       // j per chunk
constexpr int NCHUNK = 4;
constexpr int X_LD  = 68;      // padded jj-stride for X (floats)
constexpr int XOFF2 = 2180;    // padded d-plane stride for X (floats)
constexpr int ZOFF  = 2048;    // d-plane stride for Z (floats), jj stride 64

// dynamic smem (floats)
constexpr int OFF_A   = 0;                        // 64*66 f2 = 8448 f (aliased as U/W buffers during loop)
constexpr int OFF_RHS = OFF_A + 64 * A_LD * 2;    // 2048 f
constexpr int OFF_XRE = OFF_RHS + 64 * NRHS * 2;  // 2*2180 = 4360 f
constexpr int OFF_XIM = OFF_XRE + 2 * XOFF2;      // 4360 f
constexpr int OFF_ZRE = OFF_XIM + 2 * XOFF2;      // 4096 f
constexpr int OFF_ZIM = OFF_ZRE + 4096;           // 4096 f
constexpr int SMEM_FLOATS = OFF_ZIM + 4096;
constexpr size_t SMEM_BYTES = (size_t)SMEM_FLOATS * 4;

// aliased layout inside sA region during the main loop:
constexpr int UBUF_F2 = 256;    // float2 per buffer
constexpr int WBUF_F  = 128;

typedef unsigned long long u64t;
}

__device__ __forceinline__ u64t pk2(float x, float y) {
    u64t r; asm("mov.b64 %0,{%1,%2};" : "=l"(r) : "f"(x), "f"(y)); return r;
}
__device__ __forceinline__ void f2fma(u64t& d, u64t a, u64t b) {
    asm("fma.rn.f32x2 %0,%1,%2,%0;" : "+l"(d) : "l"(a), "l"(b));
}
__device__ __forceinline__ float2 up2(u64t v) {
    float2 f; asm("mov.b64 {%0,%1},%2;" : "=f"(f.x), "=f"(f.y) : "l"(v)); return f;
}
__device__ __forceinline__ float2 cmul(float2 a, float2 b) {
    return make_float2(a.x * b.x - a.y * b.y, a.x * b.y + a.y * b.x);
}

__global__ void __launch_bounds__(THREADS, 2)
uw2v_kernel(const float* __restrict__ channel,
            const float* __restrict__ pred,
            float2* __restrict__ out)
{
    extern __shared__ float smf[];
    float2* sA   = (float2*)(smf + OFF_A);
    float2* srhs = (float2*)(smf + OFF_RHS);
    float*  sxre = smf + OFF_XRE;
    float*  sxim = smf + OFF_XIM;
    float*  szre = smf + OFF_ZRE;
    float*  szim = smf + OFF_ZIM;
    // double-buffered U/W aliased into the (loop-dead) sA region
    float2* suB  = (float2*)(smf + OFF_A);            // [2][256] float2
    float*  swB  = smf + OFF_A + 2 * UBUF_F2 * 2;     // [2][128] float

    __shared__ float2 wpart[16];
    __shared__ float  s_scale;

    const int b   = blockIdx.x;
    const int tid = threadIdx.x;
    const float* ch = channel + (size_t)b * CH_STRIDE;
    const float* pr = pred    + (size_t)b * PRED_STRIDE;

    const int warp = tid >> 5, lane = tid & 31;
    const int group = tid >> 8;          // 0/1: jj-split halves
    const int gtid  = tid & 255;
    const int ty = gtid >> 4, tx = gtid & 15;
    const int t0 = ty * 4, s0 = tx * 4;

    // phase-B mapping: warp spans only 4 t values -> 4-line LDG.128
    const int pb_t  = tid >> 3;
    const int pb_fl = (tid >> 2) & 1;
    const int pb_kh = (tid >> 1) & 1;
    const int pb_d  = tid & 1;

    u64t accre[2][4], accim[2][4];
    #pragma unroll
    for (int p = 0; p < 2; p++)
        #pragma unroll
        for (int s = 0; s < 4; s++) { accre[p][s] = 0ull; accim[p][s] = 0ull; }

    float2 rhsacc[2] = {{0,0},{0,0}};
    float trre = 0.f, trim = 0.f;

    // ---- preload chunk 0 U/W into buffer 0 ----
    if (tid < 256) {
        int rd = tid >> 5, jj = tid & 31;
        int f = (jj >> 3), k = jj & 7;
        int base = (rd * 16 + f) * 16 + k;
        suB[tid] = make_float2(pr[base], pr[base + 8]);
        if (tid < 128) {
            int jw = tid >> 2, de = tid & 3;
            int fw = (jw >> 3), kw = jw & 7;
            swB[tid] = pr[NU + (de * 16 + fw) * 8 + kw];
        }
    }
    __syncthreads();

    for (int c = 0; c < NCHUNK; c++) {
        const int cur = c & 1, nxt = cur ^ 1;
        float2* su = suB + cur * UBUF_F2;
        float*  sw = swB + cur * WBUF_F;

        // ---- (B) X[d][jj][t] = sum_r conj(H)*U  (coalesced 4-line loads) ----
        #pragma unroll
        for (int fh = 0; fh < 2; fh++) {
            const int flg = fh * 2 + pb_fl;   // 0..3
            const float* chp = ch + pb_t * 1024 + (c * 4 + flg) * 16 + pb_kh * 4;
            float xr[4] = {0.f,0.f,0.f,0.f}, xi[4] = {0.f,0.f,0.f,0.f};
            #pragma unroll
            for (int r = 0; r < 4; r++) {
                float4 hre = *(const float4*)(chp + r * 256);
                float4 him = *(const float4*)(chp + r * 256 + 8);
                const float2* uptr = su + (r * 2 + pb_d) * 32 + flg * 8 + pb_kh * 4;
                float hr[4] = {hre.x, hre.y, hre.z, hre.w};
                float hi[4] = {him.x, him.y, him.z, him.w};
                #pragma unroll
                for (int kk = 0; kk < 4; kk++) {
                    float2 u = uptr[kk];
                    xr[kk] += hr[kk] * u.x + hi[kk] * u.y;
                    xi[kk] += hr[kk] * u.y - hi[kk] * u.x;
                }
            }
            #pragma unroll
            for (int kk = 0; kk < 4; kk++) {
                int jj = flg * 8 + pb_kh * 4 + kk;
                sxre[pb_d * XOFF2 + jj * X_LD + pb_t] = xr[kk];
                sxim[pb_d * XOFF2 + jj * X_LD + pb_t] = xi[kk];
            }
        }
        // ---- prefetch next chunk's U/W into the other buffer ----
        if (c + 1 < NCHUNK && tid < 256) {
            int rd = tid >> 5, jj = tid & 31;
            int f = (c + 1) * 4 + (jj >> 3), k = jj & 7;
            int base = (rd * 16 + f) * 16 + k;
            suB[nxt * UBUF_F2 + tid] = make_float2(pr[base], pr[base + 8]);
            if (tid < 128) {
                int jw = tid >> 2, de = tid & 3;
                int fw = (c + 1) * 4 + (jw >> 3), kw = jw & 7;
                swB[nxt * WBUF_F + tid] = pr[NU + (de * 16 + fw) * 8 + kw];
            }
        }
        __syncthreads();

        // ---- (C) Z = W*conj(X) vectorized, rhs accumulate, trU accumulate ----
        #pragma unroll
        for (int h = 0; h < 4; h++) {
            int idx2 = tid + 512 * h;                 // d(1)|jj(5)|sp(5)
            int d = idx2 >> 10, jj = (idx2 >> 5) & 31, sp = (idx2 & 31) * 2;
            float w0 = sw[jj * 4 + d * 2];
            float w1 = sw[jj * 4 + d * 2 + 1];
            float2 x0r = *(const float2*)(sxre + jj * X_LD + sp);
            float2 x1r = *(const float2*)(sxre + XOFF2 + jj * X_LD + sp);
            float2 x0i = *(const float2*)(sxim + jj * X_LD + sp);
            float2 x1i = *(const float2*)(sxim + XOFF2 + jj * X_LD + sp);
            int zidx = d * ZOFF + jj * 64 + sp;
            *(float2*)(szre + zidx) = make_float2(w0 * x0r.x + w1 * x1r.x,
                                                  w0 * x0r.y + w1 * x1r.y);
            *(float2*)(szim + zidx) = make_float2(-(w0 * x0i.x + w1 * x1i.x),
                                                  -(w0 * x0i.y + w1 * x1i.y));
        }
        #pragma unroll
        for (int q = 0; q < 2; q++) {
            int item = tid + 512 * q;
            int t = item >> 4, cc = item & 15, e = cc >> 3, k = cc & 7;
            float sxr = 0.f, sxi = 0.f;
            #pragma unroll
            for (int fl = 0; fl < 4; fl++) {
                int jj = fl * 8 + k;
                float w0 = sw[jj * 4 + e];
                float w1 = sw[jj * 4 + 2 + e];
                sxr += sxre[jj * X_LD + t] * w0 + sxre[XOFF2 + jj * X_LD + t] * w1;
                sxi += sxim[jj * X_LD + t] * w0 + sxim[XOFF2 + jj * X_LD + t] * w1;
            }
            rhsacc[q].x += sxr; rhsacc[q].y += sxi;
        }
        if (tid < 128) {
            int r = tid >> 5, jj = tid & 31;
            float2 u0 = su[(r * 2) * 32 + jj];
            float2 u1 = su[(r * 2 + 1) * 32 + jj];
            const float* wj = sw + jj * 4;
            float cr = u0.x * u1.x + u0.y * u1.y;
            float ci = u0.y * u1.x - u0.x * u1.y;
            trre += wj[0] * (u0.x*u0.x + u0.y*u0.y) + wj[3] * (u1.x*u1.x + u1.y*u1.y)
                  + (wj[1] + wj[2]) * cr;
            trim += (wj[1] - wj[2]) * ci;
        }
        __syncthreads();

        // ---- (D) quad GEMM: group handles its 16 jj with 4x4 tile ----
        {
            const int jb = group * 16, je = jb + 16;
            #pragma unroll 1
            for (int jj = jb; jj < je; jj++) {
                #pragma unroll
                for (int d = 0; d < 2; d++) {
                    ulonglong2 ar = *(const ulonglong2*)(sxre + d * XOFF2 + jj * X_LD + t0);
                    ulonglong2 ai = *(const ulonglong2*)(sxim + d * XOFF2 + jj * X_LD + t0);
                    float4 zr = *(const float4*)(szre + d * ZOFF + jj * 64 + s0);
                    float4 zi = *(const float4*)(szim + d * ZOFF + jj * 64 + s0);
                    float zra[4] = {zr.x, zr.y, zr.z, zr.w};
                    float zia[4] = {zi.x, zi.y, zi.z, zi.w};
                    #pragma unroll
                    for (int s = 0; s < 4; s++) {
                        u64t Zr  = pk2(zra[s], zra[s]);
                        u64t Zi  = pk2(zia[s], zia[s]);
                        u64t Zni = pk2(-zia[s], -zia[s]);
                        f2fma(accre[0][s], ar.x, Zr);  f2fma(accre[0][s], ai.x, Zni);
                        f2fma(accim[0][s], ar.x, Zi);  f2fma(accim[0][s], ai.x, Zr);
                        f2fma(accre[1][s], ar.y, Zr);  f2fma(accre[1][s], ai.y, Zni);
                        f2fma(accim[1][s], ar.y, Zi);  f2fma(accim[1][s], ai.y, Zr);
                    }
                }
            }
        }
        __syncthreads();
    }

    // ---- trU warp reduce + group-1 partial store + rhs store ----
    #pragma unroll
    for (int o = 16; o; o >>= 1) {
        trre += __shfl_down_sync(0xffffffffu, trre, o);
        trim += __shfl_down_sync(0xffffffffu, trim, o);
    }
    if (lane == 0) wpart[warp] = make_float2(trre, trim);

    u64t* scratch = (u64t*)(smf + OFF_XRE);   // X/Z region reuse
    if (group == 1) {
        int base = gtid * 32;
        #pragma unroll
        for (int p = 0; p < 2; p++)
            #pragma unroll
            for (int s = 0; s < 4; s++) {
                scratch[base + p * 4 + s]     = accre[p][s];
                scratch[base + 8 + p * 4 + s] = accim[p][s];
            }
    }
    #pragma unroll
    for (int q = 0; q < 2; q++) srhs[tid + 512 * q] = rhsacc[q];
    __syncthreads();

    // ---- group 0 merges partials, writes A (+ trU*I) ----
    if (group == 0) {
        float sx = 0.f, sy = 0.f;
        #pragma unroll
        for (int i = 0; i < 16; i++) { sx += wpart[i].x; sy += wpart[i].y; }
        float2 trU = make_float2(0.1f * sx, 0.1f * sy);
        int base = gtid * 32;
        #pragma unroll
        for (int p = 0; p < 2; p++)
            #pragma unroll
            for (int s = 0; s < 4; s++) {
                float2 re2 = up2(accre[p][s]);
                float2 im2 = up2(accim[p][s]);
                float2 ore = up2(scratch[base + p * 4 + s]);
                float2 oim = up2(scratch[base + 8 + p * 4 + s]);
                re2.x += ore.x; re2.y += ore.y;
                im2.x += oim.x; im2.y += oim.y;
                int t = t0 + p * 2, col = s0 + s;
                float2 v0 = make_float2(re2.x, im2.x);
                float2 v1 = make_float2(re2.y, im2.y);
                if (t == col)     { v0.x += trU.x; v0.y += trU.y; }
                if (t + 1 == col) { v1.x += trU.x; v1.y += trU.y; }
                sA[t * A_LD + col]       = v0;
                sA[(t + 1) * A_LD + col] = v1;
            }
    }
    __syncthreads();

    // ---- blocked-4 register-resident Gauss-Jordan (no pivoting) ----
    // warp w owns rows 4w..4w+3; panel = in-warp micro-GJ over 4 cols via shfl;
    // one __syncthreads per block of 4 columns (17 barriers total).
    const int r = tid >> 3, cg = tid & 7;
    const int rl = r & 3;
    float2 a[8]; float2 rr[2];
    #pragma unroll
    for (int j = 0; j < 8; j++) a[j] = sA[r * A_LD + cg * 8 + j];
    {
        float4 t4 = *(const float4*)(srhs + r * NRHS + cg * 2);
        rr[0] = make_float2(t4.x, t4.y);
        rr[1] = make_float2(t4.z, t4.w);
    }
    // pub buffers aliased into dead X/Z scratch (solver-only)
    float2* pubA = (float2*)(smf + OFF_XRE);   // [(buf*4+rl)*82 + cg*10 + j]
    float2* pubR = pubA + 656;                 // [(buf*4+rl)*18 + cg*2 + q]

    auto panel = [&](int pb) {
        const int jbn  = (pb * 4) & 7;    // 0 or 4
        const int cgbn = (pb * 4) >> 3;
        const int buf  = pb & 1;
        #pragma unroll
        for (int m = 0; m < 4; m++) {
            float2 vsel = (jbn == 0) ? a[m] : a[m + 4];
            const int pl = m * 8 + cgbn;
            const int fl2 = rl * 8 + cgbn;
            float2 dv, fr;
            dv.x = __shfl_sync(0xffffffffu, vsel.x, pl);
            dv.y = __shfl_sync(0xffffffffu, vsel.y, pl);
            fr.x = __shfl_sync(0xffffffffu, vsel.x, fl2);
            fr.y = __shfl_sync(0xffffffffu, vsel.y, fl2);
            float inv = 1.f / (dv.x * dv.x + dv.y * dv.y);
            float2 pinv = make_float2(dv.x * inv, -dv.y * inv);
            float2 f = cmul(fr, pinv);
            const bool ispiv = (rl == m);
            const int sl = m * 8 + cg;
            #pragma unroll
            for (int j = 0; j < 8; j++) {
                float2 pj;
                pj.x = __shfl_sync(0xffffffffu, a[j].x, sl);
                pj.y = __shfl_sync(0xffffffffu, a[j].y, sl);
                a[j] = ispiv ? cmul(a[j], pinv)
                             : make_float2(a[j].x - (f.x * pj.x - f.y * pj.y),
                                           a[j].y - (f.x * pj.y + f.y * pj.x));
            }
            #pragma unroll
            for (int q = 0; q < 2; q++) {
                float2 pq;
                pq.x = __shfl_sync(0xffffffffu, rr[q].x, sl);
                pq.y = __shfl_sync(0xffffffffu, rr[q].y, sl);
                rr[q] = ispiv ? cmul(rr[q], pinv)
                              : make_float2(rr[q].x - (f.x * pq.x - f.y * pq.y),
                                            rr[q].y - (f.x * pq.y + f.y * pq.x));
            }
        }
        float2* dstA = pubA + (buf * 4 + rl) * 82 + cg * 10;
        #pragma unroll
        for (int j = 0; j < 8; j++) dstA[j] = a[j];
        float2* dstR = pubR + (buf * 4 + rl) * 18 + cg * 2;
        dstR[0] = rr[0];
        dstR[1] = rr[1];
    };

    if (warp == 0) panel(0);
    __syncthreads();

    #pragma unroll 1
    for (int blk = 0; blk < 16; blk++) {
        const int buf = blk & 1;
        if (warp != blk) {
            const int cgb = (blk * 4) >> 3;
            const int jb0 = (blk * 4) & 7;
            const int srcl = (rl << 3) | cgb;
            float2 g[4];
            #pragma unroll
            for (int m = 0; m < 4; m++) {
                float2 v = (jb0 == 0) ? a[m] : a[m + 4];
                g[m].x = __shfl_sync(0xffffffffu, v.x, srcl);
                g[m].y = __shfl_sync(0xffffffffu, v.y, srcl);
            }
            #pragma unroll
            for (int m = 0; m < 4; m++) {
                const float2* P = pubA + (buf * 4 + m) * 82 + cg * 10;
                const float2 gm = g[m];
                #pragma unroll
                for (int jp = 0; jp < 4; jp++) {
                    float4 pq = *(const float4*)(P + jp * 2);
                    a[jp*2].x   -= gm.x * pq.x - gm.y * pq.y;
                    a[jp*2].y   -= gm.x * pq.y + gm.y * pq.x;
                    a[jp*2+1].x -= gm.x * pq.z - gm.y * pq.w;
                    a[jp*2+1].y -= gm.x * pq.w + gm.y * pq.z;
                }
                float4 qq = *(const float4*)(pubR + (buf * 4 + m) * 18 + cg * 2);
                rr[0].x -= gm.x * qq.x - gm.y * qq.y;
                rr[0].y -= gm.x * qq.y + gm.y * qq.x;
                rr[1].x -= gm.x * qq.z - gm.y * qq.w;
                rr[1].y -= gm.x * qq.w + gm.y * qq.z;
            }
        }
        if (blk + 1 < 16 && warp == blk + 1) panel(blk + 1);
        __syncthreads();
    }

    // ---- scatter solution: X[r] = this row's rhs (no pivoting -> row == col) ----
    *(float4*)(srhs + r * NRHS + cg * 2) =
        make_float4(rr[0].x, rr[0].y, rr[1].x, rr[1].y);
    __syncthreads();

    // ---- normalize + write out ----
    float ss = 0.f;
    #pragma unroll
    for (int q = 0; q < 2; q++) {
        float2 v = srhs[tid + 512 * q];
        ss += v.x * v.x + v.y * v.y;
    }
    #pragma unroll
    for (int o = 16; o; o >>= 1) ss += __shfl_down_sync(0xffffffffu, ss, o);
    if (lane == 0) wpart[warp].x = ss;
    __syncthreads();
    if (tid == 0) {
        float tot = 0.f;
        #pragma unroll
        for (int i = 0; i < 16; i++) tot += wpart[i].x;
        s_scale = rsqrtf(tot);   // P=1: total factor = 1/||V0||
    }
    __syncthreads();
    const float sc = s_scale;
    float2* op = out + (size_t)b * (64 * NRHS);
    #pragma unroll
    for (int q = 0; q < 2; q++) {
        float2 v = srhs[tid + 512 * q];
        op[tid + 512 * q] = make_float2(v.x * sc, v.y * sc);
    }
}

extern "C" void kernel_launch(void* const* d_in, const int* in_sizes, int n_in,
                              void* d_out, int out_size)
{
    const float* channel = (const float*)d_in[0];
    const float* pred    = (const float*)d_in[1];
    cudaFuncSetAttribute(uw2v_kernel, cudaFuncAttributeMaxDynamicSharedMemorySize,
                         (int)SMEM_BYTES);
    uw2v_kernel<<<256, THREADS, SMEM_BYTES, 0>>>(channel, pred, (float2*)d_out);
}

// round 17
// speedup vs baseline: 1.0198x; 1.0198x over previous
#include <cuda_runtime.h>

namespace {
constexpr int THREADS = 512;
constexpr int CH_STRIDE = 64 * 4 * 16 * 2 * 8;     // 65536 floats / batch
constexpr int NU = 2 * 4 * 2 * 8 * 16;             // 2048
constexpr int PRED_STRIDE = NU + 2 * 2 * 8 * 16;   // 2560
constexpr int A_LD = 66;
constexpr int NRHS = 16;
constexpr int CH_J = 32;       // j per chunk
constexpr int NCHUNK = 4;
constexpr int X_LD  = 68;      // padded jj-stride for X (floats)
constexpr int XOFF2 = 2180;    // padded d-plane stride for X (floats)
constexpr int ZOFF  = 2048;    // d-plane stride for Z (floats), jj stride 64

// dynamic smem (floats)
constexpr int OFF_A   = 0;                        // 64*66 f2 = 8448 f (aliased as U/W buffers during loop)
constexpr int OFF_RHS = OFF_A + 64 * A_LD * 2;    // 2048 f
constexpr int OFF_XRE = OFF_RHS + 64 * NRHS * 2;  // 2*2180 = 4360 f
constexpr int OFF_XIM = OFF_XRE + 2 * XOFF2;      // 4360 f
constexpr int OFF_ZRE = OFF_XIM + 2 * XOFF2;      // 4096 f
constexpr int OFF_ZIM = OFF_ZRE + 4096;           // 4096 f
constexpr int SMEM_FLOATS = OFF_ZIM + 4096;
constexpr size_t SMEM_BYTES = (size_t)SMEM_FLOATS * 4;

// aliased layout inside sA region during the main loop:
constexpr int UBUF_F2 = 256;    // float2 per buffer
constexpr int WBUF_F  = 128;

typedef unsigned long long u64t;
}

__device__ __forceinline__ u64t pk2(float x, float y) {
    u64t r; asm("mov.b64 %0,{%1,%2};" : "=l"(r) : "f"(x), "f"(y)); return r;
}
__device__ __forceinline__ void f2fma(u64t& d, u64t a, u64t b) {
    asm("fma.rn.f32x2 %0,%1,%2,%0;" : "+l"(d) : "l"(a), "l"(b));
}
__device__ __forceinline__ float2 up2(u64t v) {
    float2 f; asm("mov.b64 {%0,%1},%2;" : "=f"(f.x), "=f"(f.y) : "l"(v)); return f;
}

__global__ void __launch_bounds__(THREADS, 2)
uw2v_kernel(const float* __restrict__ channel,
            const float* __restrict__ pred,
            float2* __restrict__ out)
{
    extern __shared__ float smf[];
    float2* sA   = (float2*)(smf + OFF_A);
    float2* srhs = (float2*)(smf + OFF_RHS);
    float*  sxre = smf + OFF_XRE;
    float*  sxim = smf + OFF_XIM;
    float*  szre = smf + OFF_ZRE;
    float*  szim = smf + OFF_ZIM;
    // double-buffered U/W aliased into the (loop-dead) sA region
    float2* suB  = (float2*)(smf + OFF_A);            // [2][256] float2
    float*  swB  = smf + OFF_A + 2 * UBUF_F2 * 2;     // [2][128] float

    __shared__ __align__(16) float2 prow[2][80];   // double-buffered, stride-10 skew
    __shared__ __align__(16) float2 prhs[2][16];
    __shared__ float2 wpart[16];
    __shared__ float  s_scale;

    const int b   = blockIdx.x;
    const int tid = threadIdx.x;
    const float* ch = channel + (size_t)b * CH_STRIDE;
    const float* pr = pred    + (size_t)b * PRED_STRIDE;

    const int warp = tid >> 5, lane = tid & 31;
    const int group = tid >> 8;          // 0/1: jj-split halves
    const int gtid  = tid & 255;
    const int ty = gtid >> 4, tx = gtid & 15;
    const int t0 = ty * 4, s0 = tx * 4;

    // phase-B mapping: warp spans only 4 t values -> 4-line LDG.128
    const int pb_t  = tid >> 3;
    const int pb_fl = (tid >> 2) & 1;
    const int pb_kh = (tid >> 1) & 1;
    const int pb_d  = tid & 1;

    u64t accre[2][4], accim[2][4];
    #pragma unroll
    for (int p = 0; p < 2; p++)
        #pragma unroll
        for (int s = 0; s < 4; s++) { accre[p][s] = 0ull; accim[p][s] = 0ull; }

    float2 rhsacc[2] = {{0,0},{0,0}};
    float trre = 0.f, trim = 0.f;

    // ---- preload chunk 0 U/W into buffer 0 ----
    if (tid < 256) {
        int rd = tid >> 5, jj = tid & 31;
        int f = (jj >> 3), k = jj & 7;
        int base = (rd * 16 + f) * 16 + k;
        suB[tid] = make_float2(pr[base], pr[base + 8]);
        if (tid < 128) {
            int jw = tid >> 2, de = tid & 3;
            int fw = (jw >> 3), kw = jw & 7;
            swB[tid] = pr[NU + (de * 16 + fw) * 8 + kw];
        }
    }
    __syncthreads();

    for (int c = 0; c < NCHUNK; c++) {
        const int cur = c & 1, nxt = cur ^ 1;
        float2* su = suB + cur * UBUF_F2;
        float*  sw = swB + cur * WBUF_F;

        // ---- (B) X[d][jj][t] = sum_r conj(H)*U  (coalesced 4-line loads) ----
        #pragma unroll
        for (int fh = 0; fh < 2; fh++) {
            const int flg = fh * 2 + pb_fl;   // 0..3
            const float* chp = ch + pb_t * 1024 + (c * 4 + flg) * 16 + pb_kh * 4;
            float xr[4] = {0.f,0.f,0.f,0.f}, xi[4] = {0.f,0.f,0.f,0.f};
            #pragma unroll
            for (int r = 0; r < 4; r++) {
                float4 hre = *(const float4*)(chp + r * 256);
                float4 him = *(const float4*)(chp + r * 256 + 8);
                const float2* uptr = su + (r * 2 + pb_d) * 32 + flg * 8 + pb_kh * 4;
                float hr[4] = {hre.x, hre.y, hre.z, hre.w};
                float hi[4] = {him.x, him.y, him.z, him.w};
                #pragma unroll
                for (int kk = 0; kk < 4; kk++) {
                    float2 u = uptr[kk];
                    xr[kk] += hr[kk] * u.x + hi[kk] * u.y;
                    xi[kk] += hr[kk] * u.y - hi[kk] * u.x;
                }
            }
            #pragma unroll
            for (int kk = 0; kk < 4; kk++) {
                int jj = flg * 8 + pb_kh * 4 + kk;
                sxre[pb_d * XOFF2 + jj * X_LD + pb_t] = xr[kk];
                sxim[pb_d * XOFF2 + jj * X_LD + pb_t] = xi[kk];
            }
        }
        // ---- prefetch next chunk's U/W into the other buffer ----
        if (c + 1 < NCHUNK && tid < 256) {
            int rd = tid >> 5, jj = tid & 31;
            int f = (c + 1) * 4 + (jj >> 3), k = jj & 7;
            int base = (rd * 16 + f) * 16 + k;
            suB[nxt * UBUF_F2 + tid] = make_float2(pr[base], pr[base + 8]);
            if (tid < 128) {
                int jw = tid >> 2, de = tid & 3;
                int fw = (c + 1) * 4 + (jw >> 3), kw = jw & 7;
                swB[nxt * WBUF_F + tid] = pr[NU + (de * 16 + fw) * 8 + kw];
            }
        }
        __syncthreads();

        // ---- (C) Z = W*conj(X): both d per item (one X read pair serves both planes) ----
        #pragma unroll
        for (int h = 0; h < 2; h++) {
            int item = tid + 512 * h;                 // jj(5)|sp2(5)
            int jj = item >> 5, sp = (item & 31) * 2;
            float w00 = sw[jj * 4 + 0];
            float w01 = sw[jj * 4 + 1];
            float w10 = sw[jj * 4 + 2];
            float w11 = sw[jj * 4 + 3];
            float2 x0r = *(const float2*)(sxre + jj * X_LD + sp);
            float2 x1r = *(const float2*)(sxre + XOFF2 + jj * X_LD + sp);
            float2 x0i = *(const float2*)(sxim + jj * X_LD + sp);
            float2 x1i = *(const float2*)(sxim + XOFF2 + jj * X_LD + sp);
            int zidx = jj * 64 + sp;
            *(float2*)(szre + zidx) = make_float2(w00 * x0r.x + w01 * x1r.x,
                                                  w00 * x0r.y + w01 * x1r.y);
            *(float2*)(szim + zidx) = make_float2(-(w00 * x0i.x + w01 * x1i.x),
                                                  -(w00 * x0i.y + w01 * x1i.y));
            *(float2*)(szre + ZOFF + zidx) = make_float2(w10 * x0r.x + w11 * x1r.x,
                                                         w10 * x0r.y + w11 * x1r.y);
            *(float2*)(szim + ZOFF + zidx) = make_float2(-(w10 * x0i.x + w11 * x1i.x),
                                                         -(w10 * x0i.y + w11 * x1i.y));
        }
        #pragma unroll
        for (int q = 0; q < 2; q++) {
            int item = tid + 512 * q;
            int t = item >> 4, cc = item & 15, e = cc >> 3, k = cc & 7;
            float sxr = 0.f, sxi = 0.f;
            #pragma unroll
            for (int fl = 0; fl < 4; fl++) {
                int jj = fl * 8 + k;
                float w0 = sw[jj * 4 + e];
                float w1 = sw[jj * 4 + 2 + e];
                sxr += sxre[jj * X_LD + t] * w0 + sxre[XOFF2 + jj * X_LD + t] * w1;
                sxi += sxim[jj * X_LD + t] * w0 + sxim[XOFF2 + jj * X_LD + t] * w1;
            }
            rhsacc[q].x += sxr; rhsacc[q].y += sxi;
        }
        if (tid < 128) {
            int r = tid >> 5, jj = tid & 31;
            float2 u0 = su[(r * 2) * 32 + jj];
            float2 u1 = su[(r * 2 + 1) * 32 + jj];
            const float* wj = sw + jj * 4;
            float cr = u0.x * u1.x + u0.y * u1.y;
            float ci = u0.y * u1.x - u0.x * u1.y;
            trre += wj[0] * (u0.x*u0.x + u0.y*u0.y) + wj[3] * (u1.x*u1.x + u1.y*u1.y)
                  + (wj[1] + wj[2]) * cr;
            trim += (wj[1] - wj[2]) * ci;
        }
        __syncthreads();

        // ---- (D) quad GEMM: group handles its 16 jj with 4x4 tile ----
        {
            const int jb = group * 16, je = jb + 16;
            #pragma unroll 1
            for (int jj = jb; jj < je; jj++) {
                #pragma unroll
                for (int d = 0; d < 2; d++) {
                    ulonglong2 ar = *(const ulonglong2*)(sxre + d * XOFF2 + jj * X_LD + t0);
                    ulonglong2 ai = *(const ulonglong2*)(sxim + d * XOFF2 + jj * X_LD + t0);
                    float4 zr = *(const float4*)(szre + d * ZOFF + jj * 64 + s0);
                    float4 zi = *(const float4*)(szim + d * ZOFF + jj * 64 + s0);
                    float zra[4] = {zr.x, zr.y, zr.z, zr.w};
                    float zia[4] = {zi.x, zi.y, zi.z, zi.w};
                    #pragma unroll
                    for (int s = 0; s < 4; s++) {
                        u64t Zr  = pk2(zra[s], zra[s]);
                        u64t Zi  = pk2(zia[s], zia[s]);
                        u64t Zni = pk2(-zia[s], -zia[s]);
                        f2fma(accre[0][s], ar.x, Zr);  f2fma(accre[0][s], ai.x, Zni);
                        f2fma(accim[0][s], ar.x, Zi);  f2fma(accim[0][s], ai.x, Zr);
                        f2fma(accre[1][s], ar.y, Zr);  f2fma(accre[1][s], ai.y, Zni);
                        f2fma(accim[1][s], ar.y, Zi);  f2fma(accim[1][s], ai.y, Zr);
                    }
                }
            }
        }
        __syncthreads();
    }

    // ---- trU warp reduce + group-1 partial store + rhs store ----
    #pragma unroll
    for (int o = 16; o; o >>= 1) {
        trre += __shfl_down_sync(0xffffffffu, trre, o);
        trim += __shfl_down_sync(0xffffffffu, trim, o);
    }
    if (lane == 0) wpart[warp] = make_float2(trre, trim);

    u64t* scratch = (u64t*)(smf + OFF_XRE);   // X/Z region reuse
    if (group == 1) {
        int base = gtid * 32;
        #pragma unroll
        for (int p = 0; p < 2; p++)
            #pragma unroll
            for (int s = 0; s < 4; s++) {
                scratch[base + p * 4 + s]     = accre[p][s];
                scratch[base + 8 + p * 4 + s] = accim[p][s];
            }
    }
    #pragma unroll
    for (int q = 0; q < 2; q++) srhs[tid + 512 * q] = rhsacc[q];
    __syncthreads();

    // ---- group 0 merges partials, writes A (+ trU*I) ----
    if (group == 0) {
        float sx = 0.f, sy = 0.f;
        #pragma unroll
        for (int i = 0; i < 16; i++) { sx += wpart[i].x; sy += wpart[i].y; }
        float2 trU = make_float2(0.1f * sx, 0.1f * sy);
        int base = gtid * 32;
        #pragma unroll
        for (int p = 0; p < 2; p++)
            #pragma unroll
            for (int s = 0; s < 4; s++) {
                float2 re2 = up2(accre[p][s]);
                float2 im2 = up2(accim[p][s]);
                float2 ore = up2(scratch[base + p * 4 + s]);
                float2 oim = up2(scratch[base + 8 + p * 4 + s]);
                re2.x += ore.x; re2.y += ore.y;
                im2.x += oim.x; im2.y += oim.y;
                int t = t0 + p * 2, col = s0 + s;
                float2 v0 = make_float2(re2.x, im2.x);
                float2 v1 = make_float2(re2.y, im2.y);
                if (t == col)     { v0.x += trU.x; v0.y += trU.y; }
                if (t + 1 == col) { v1.x += trU.x; v1.y += trU.y; }
                sA[t * A_LD + col]       = v0;
                sA[(t + 1) * A_LD + col] = v1;
            }
    }
    __syncthreads();

    // ---- register-resident Gauss-Jordan, NO pivot search, 1 barrier/iter ----
    const int r = tid >> 3, cg = tid & 7;
    float2 a[8]; float2 rr[2];
    #pragma unroll
    for (int j = 0; j < 8; j++) a[j] = sA[r * A_LD + cg * 8 + j];
    {
        float4 t4 = *(const float4*)(srhs + r * NRHS + cg * 2);
        rr[0] = make_float2(t4.x, t4.y);
        rr[1] = make_float2(t4.z, t4.w);
    }
    // publish row 0 (raw) into buffer 0
    if (r == 0) {
        #pragma unroll
        for (int j = 0; j < 8; j++) prow[0][cg * 10 + j] = a[j];
        prhs[0][cg * 2]     = rr[0];
        prhs[0][cg * 2 + 1] = rr[1];
    }
    __syncthreads();

    for (int oct = 0; oct < 8; oct++) {
        #pragma unroll
        for (int jl = 0; jl < 8; jl++) {
            const int i = oct * 8 + jl;
            const int buf = i & 1, nbuf = buf ^ 1;
            // pivot element of the published (raw) row i
            float2 dv = prow[buf][oct * 10 + jl];
            float inv = 1.f / (dv.x * dv.x + dv.y * dv.y);
            float2 pinv = make_float2(dv.x * inv, -dv.y * inv);
            // in-warp broadcast of this row's column-i value
            float2 av = a[jl];
            const int srclane = ((r & 3) << 3) | oct;
            float fvx = __shfl_sync(0xffffffffu, av.x, srclane);
            float fvy = __shfl_sync(0xffffffffu, av.y, srclane);
            if (r == i) {
                // pivot row: normalize in registers
                #pragma unroll
                for (int j = 0; j < 8; j++) {
                    float2 v = a[j];
                    a[j] = make_float2(v.x * pinv.x - v.y * pinv.y,
                                       v.x * pinv.y + v.y * pinv.x);
                }
                float2 v0 = rr[0], v1 = rr[1];
                rr[0] = make_float2(v0.x * pinv.x - v0.y * pinv.y,
                                    v0.x * pinv.y + v0.y * pinv.x);
                rr[1] = make_float2(v1.x * pinv.x - v1.y * pinv.y,
                                    v1.x * pinv.y + v1.y * pinv.x);
            } else {
                float f_x = fvx * pinv.x - fvy * pinv.y;
                float f_y = fvx * pinv.y + fvy * pinv.x;
                #pragma unroll
                for (int jp = 0; jp < 4; jp++) {
                    float4 pq = *(const float4*)(prow[buf] + cg * 10 + jp * 2);
                    a[jp*2].x   -= f_x * pq.x - f_y * pq.y;
                    a[jp*2].y   -= f_x * pq.y + f_y * pq.x;
                    a[jp*2+1].x -= f_x * pq.z - f_y * pq.w;
                    a[jp*2+1].y -= f_x * pq.w + f_y * pq.z;
                }
                float4 pb = *(const float4*)(prhs[buf] + cg * 2);
                rr[0].x -= f_x * pb.x - f_y * pb.y;
                rr[0].y -= f_x * pb.y + f_y * pb.x;
                rr[1].x -= f_x * pb.z - f_y * pb.w;
                rr[1].y -= f_x * pb.w + f_y * pb.z;
                // freshly-eliminated next pivot row publishes into the other buffer
                if (r == i + 1) {
                    #pragma unroll
                    for (int j = 0; j < 8; j++) prow[nbuf][cg * 10 + j] = a[j];
                    prhs[nbuf][cg * 2]     = rr[0];
                    prhs[nbuf][cg * 2 + 1] = rr[1];
                }
            }
            __syncthreads();
        }
    }

    // ---- scatter solution: X[r] = this row's rhs ----
    *(float4*)(srhs + r * NRHS + cg * 2) =
        make_float4(rr[0].x, rr[0].y, rr[1].x, rr[1].y);
    __syncthreads();

    // ---- normalize + write out ----
    float ss = 0.f;
    #pragma unroll
    for (int q = 0; q < 2; q++) {
        float2 v = srhs[tid + 512 * q];
        ss += v.x * v.x + v.y * v.y;
    }
    #pragma unroll
    for (int o = 16; o; o >>= 1) ss += __shfl_down_sync(0xffffffffu, ss, o);
    if (lane == 0) wpart[warp].x = ss;
    __syncthreads();
    if (tid == 0) {
        float tot = 0.f;
        #pragma unroll
        for (int i = 0; i < 16; i++) tot += wpart[i].x;
        s_scale = rsqrtf(tot);   // P=1: total factor = 1/||V0||
    }
    __syncthreads();
    const float sc = s_scale;
    float2* op = out + (size_t)b * (64 * NRHS);
    #pragma unroll
    for (int q = 0; q < 2; q++) {
        float2 v = srhs[tid + 512 * q];
        op[tid + 512 * q] = make_float2(v.x * sc, v.y * sc);
    }
}

extern "C" void kernel_launch(void* const* d_in, const int* in_sizes, int n_in,
                              void* d_out, int out_size)
{
    const float* channel = (const float*)d_in[0];
    const float* pred    = (const float*)d_in[1];
    cudaFuncSetAttribute(uw2v_kernel, cudaFuncAttributeMaxDynamicSharedMemorySize,
                         (int)SMEM_BYTES);
    uw2v_kernel<<<256, THREADS, SMEM_BYTES, 0>>>(channel, pred, (float2*)d_out);
}